// round 3
// baseline (speedup 1.0000x reference)
#include <cuda_runtime.h>

typedef unsigned long long u64;

// ---- packed f32x2 helpers (sm_103a) ----
__device__ __forceinline__ u64 pack2(float lo, float hi) {
    u64 d;
    asm("mov.b64 %0, {%1, %2};" : "=l"(d) : "r"(__float_as_uint(lo)), "r"(__float_as_uint(hi)));
    return d;
}
__device__ __forceinline__ void unpack2(u64 v, float& lo, float& hi) {
    unsigned a, b;
    asm("mov.b64 {%0, %1}, %2;" : "=r"(a), "=r"(b) : "l"(v));
    lo = __uint_as_float(a); hi = __uint_as_float(b);
}
__device__ __forceinline__ u64 fma2(u64 a, u64 b, u64 c) {
    u64 d;
    asm("fma.rn.f32x2 %0, %1, %2, %3;" : "=l"(d) : "l"(a), "l"(b), "l"(c));
    return d;
}
__device__ __forceinline__ u64 mul2(u64 a, u64 b) {
    u64 d;
    asm("mul.rn.f32x2 %0, %1, %2;" : "=l"(d) : "l"(a), "l"(b));
    return d;
}
__device__ __forceinline__ u64 add2(u64 a, u64 b) {
    u64 d;
    asm("add.rn.f32x2 %0, %1, %2;" : "=l"(d) : "l"(a), "l"(b));
    return d;
}
__device__ __forceinline__ u64 relu2(u64 v) {
    float lo, hi; unpack2(v, lo, hi);          // reg-pair alias, free in SASS
    lo = fmaxf(lo, 0.0f); hi = fmaxf(hi, 0.0f);
    return pack2(lo, hi);
}

// ---- problem constants ----
constexpr int W_DIM = 4096;
constexpr int C_DIM = 64;
constexpr int L_SEG = 512;            // outputs per warp
constexpr int SEGS  = W_DIM / L_SEG;  // 8
constexpr int BH    = 16 * 21;        // 336 rows
constexpr int PF    = 8;              // x prefetch distance (steps)
constexpr int WU    = 64;             // warmup steps (need >= 52 for valid pipeline)
constexpr int T_TOT = WU + L_SEG;     // 576 total steps (multiple of 32)

// Cross-correlation, zero pad. pad_lo: d=1 -> 3, d=2 -> 7, d=4 -> 14.
// y1[w] = relu(sum_k x [w- 3+  k] * w1[k])
// y2[w] = relu(sum_k y1[w- 7+ 2k] * w2[k])   (y1 := 0 outside [0,W))
// y3[w] = relu(sum_k y2[w-14+ 4k] * w3[k])   (y2 := 0 outside [0,W))
//
// Software-pipelined schedule (per warp, lane = 2 packed channels f32x2),
// t0 = s0 - 36:
//   step i: LOAD  x position t0+i+PF          -> xr  slot (i+PF) & 15
//           STAGE1: y1 @ p1 = t0+i-4          -> y1r slot  i & 15
//                   (x slots i-7 .. i ; newest load from step i-PF)
//           STAGE2: y2 @ p2 = t0+i-12         -> y2r slot  i & 31
//                   (y1 of steps i-15,i-13,..,i-1 : newest is 1 step old)
//           STAGE3: y3 @ p3 = t0+i-28
//                   (y2 of steps i-30,i-26,..,i-2 : newest is 2 steps old)
//           STORE p3 = s0 + (i - WU), valid for all i in [WU, T_TOT).
// The three stage chains are independent within a step -> 3x ILP.

#define LOAD_STEP(i, u)                                                        \
    {                                                                          \
        u64 xv;                                                                \
        if (BOUNDARY) {                                                        \
            const int t = t0 + (i) + PF;                                       \
            xv = (t >= 0 && t < W_DIM)                                         \
               ? *(const u64*)(ld_base + (long long)((i) + PF) * C_DIM) : 0ull;\
        } else {                                                               \
            xv = *(const u64*)(ld_base + (long long)((i) + PF) * C_DIM);       \
        }                                                                      \
        xr[((u) + PF) & 15] = xv;                                              \
    }

#define STAGE1(i, u)                                                           \
    {                                                                          \
        u64 a0 = mul2(xr[((u) - 7) & 15], w1r[0]);                             \
        u64 a1 = mul2(xr[((u) - 6) & 15], w1r[1]);                             \
        a0 = fma2(xr[((u) - 5) & 15], w1r[2], a0);                             \
        a1 = fma2(xr[((u) - 4) & 15], w1r[3], a1);                             \
        a0 = fma2(xr[((u) - 3) & 15], w1r[4], a0);                             \
        a1 = fma2(xr[((u) - 2) & 15], w1r[5], a1);                             \
        a0 = fma2(xr[((u) - 1) & 15], w1r[6], a0);                             \
        a1 = fma2(xr[((u) - 0) & 15], w1r[7], a1);                             \
        u64 y1v = relu2(add2(a0, a1));                                         \
        if (BOUNDARY) {                                                        \
            const int p1 = t0 + (i) - 4;                                       \
            if (p1 < 0 || p1 >= W_DIM) y1v = 0ull;                             \
        }                                                                      \
        y1r[(u) & 15] = y1v;                                                   \
    }

#define STAGE2(i, u)                                                           \
    {                                                                          \
        u64 b0 = mul2(y1r[((u) - 15) & 15], w2r[0]);                           \
        u64 b1 = mul2(y1r[((u) - 13) & 15], w2r[1]);                           \
        b0 = fma2(y1r[((u) - 11) & 15], w2r[2], b0);                           \
        b1 = fma2(y1r[((u) -  9) & 15], w2r[3], b1);                           \
        b0 = fma2(y1r[((u) -  7) & 15], w2r[4], b0);                           \
        b1 = fma2(y1r[((u) -  5) & 15], w2r[5], b1);                           \
        b0 = fma2(y1r[((u) -  3) & 15], w2r[6], b0);                           \
        b1 = fma2(y1r[((u) -  1) & 15], w2r[7], b1);                           \
        u64 y2v = relu2(add2(b0, b1));                                         \
        if (BOUNDARY) {                                                        \
            const int p2 = t0 + (i) - 12;                                      \
            if (p2 < 0 || p2 >= W_DIM) y2v = 0ull;                             \
        }                                                                      \
        y2r[(u) & 31] = y2v;                                                   \
    }

#define STAGE3_STORE(i, u)                                                     \
    {                                                                          \
        u64 c0 = mul2(y2r[((u) - 30) & 31], w3r[0]);                           \
        u64 c1 = mul2(y2r[((u) - 26) & 31], w3r[1]);                           \
        c0 = fma2(y2r[((u) - 22) & 31], w3r[2], c0);                           \
        c1 = fma2(y2r[((u) - 18) & 31], w3r[3], c1);                           \
        c0 = fma2(y2r[((u) - 14) & 31], w3r[4], c0);                           \
        c1 = fma2(y2r[((u) - 10) & 31], w3r[5], c1);                           \
        c0 = fma2(y2r[((u) -  6) & 31], w3r[6], c0);                           \
        c1 = fma2(y2r[((u) -  2) & 31], w3r[7], c1);                           \
        const u64 y3v = relu2(add2(c0, c1));                                   \
        __stcs((u64*)(st_base + (long long)(i) * C_DIM), y3v);                 \
    }

template<bool BOUNDARY>
__device__ __forceinline__ void run_seg(
    const float* __restrict__ x,
    const u64* w1r, const u64* w2r, const u64* w3r,
    float* __restrict__ out,
    int bh, int seg, int lane)
{
    const int s0 = seg * L_SEG;
    const int t0 = s0 - 36;

    const float* ld_base = x   + ((long long)bh * W_DIM + t0) * C_DIM + 2 * lane;
    float*       st_base = out + ((long long)bh * W_DIM + (s0 - WU)) * C_DIM + 2 * lane;

    u64 xr[16], y1r[16], y2r[32];
    #pragma unroll
    for (int j = 0; j < 16; ++j) xr[j]  = 0ull;
    #pragma unroll
    for (int j = 0; j < 16; ++j) y1r[j] = 0ull;
    #pragma unroll
    for (int j = 0; j < 32; ++j) y2r[j] = 0ull;

    // preload positions 0..PF-1 into slots 0..PF-1
    #pragma unroll
    for (int j = 0; j < PF; ++j) {
        if (BOUNDARY) {
            const int t = t0 + j;
            xr[j] = (t >= 0 && t < W_DIM)
                  ? *(const u64*)(ld_base + (long long)j * C_DIM) : 0ull;
        } else {
            xr[j] = *(const u64*)(ld_base + (long long)j * C_DIM);
        }
    }

    // warmup: stages 1-2 only (fills y1/y2 rings; y3 would be garbage anyway)
    for (int ib = 0; ib < WU; ib += 32) {
        #pragma unroll
        for (int u = 0; u < 32; ++u) {
            const int i = ib + u;
            LOAD_STEP(i, u)
            STAGE1(i, u)
            STAGE2(i, u)
        }
    }

    // main: all stages, unconditional store (p3 in [s0, s0+L) for every step)
    for (int ib = WU; ib < T_TOT; ib += 32) {
        #pragma unroll
        for (int u = 0; u < 32; ++u) {
            const int i = ib + u;
            LOAD_STEP(i, u)
            STAGE1(i, u)
            STAGE2(i, u)
            STAGE3_STORE(i, u)
        }
    }
}

__global__ void __launch_bounds__(128)
conv_stack_kernel(const float* __restrict__ x,
                  const float* __restrict__ w1,
                  const float* __restrict__ w2,
                  const float* __restrict__ w3,
                  float* __restrict__ out)
{
    const int warp = blockIdx.x * 4 + (threadIdx.x >> 5);
    const int lane = threadIdx.x & 31;

    const int bh  = warp >> 3;        // warp / SEGS
    const int seg = warp & 7;         // warp % SEGS

    // per-channel-pair weights (8 taps each), contiguous float2 at k*64 + 2*lane
    u64 w1r[8], w2r[8], w3r[8];
    #pragma unroll
    for (int k = 0; k < 8; ++k) {
        w1r[k] = *(const u64*)(w1 + k * C_DIM + 2 * lane);
        w2r[k] = *(const u64*)(w2 + k * C_DIM + 2 * lane);
        w3r[k] = *(const u64*)(w3 + k * C_DIM + 2 * lane);
    }

    if (seg == 0 || seg == SEGS - 1) {
        run_seg<true >(x, w1r, w2r, w3r, out, bh, seg, lane);
    } else {
        run_seg<false>(x, w1r, w2r, w3r, out, bh, seg, lane);
    }
}

extern "C" void kernel_launch(void* const* d_in, const int* in_sizes, int n_in,
                              void* d_out, int out_size)
{
    const float* x  = (const float*)d_in[0];
    const float* w1 = (const float*)d_in[1];
    const float* w2 = (const float*)d_in[2];
    const float* w3 = (const float*)d_in[3];
    float* out = (float*)d_out;

    (void)in_sizes; (void)n_in; (void)out_size;

    // 336 rows * 8 segs = 2688 warps -> 672 blocks of 128 threads, one launch
    conv_stack_kernel<<<(BH * SEGS) / 4, 128>>>(x, w1, w2, w3, out);
}